// round 3
// baseline (speedup 1.0000x reference)
#include <cuda_runtime.h>

#define NS 10
#define ND 32
#define NL 4
#define NB 1024

// ---- packed f32x2 helpers (sm_103a) ----
__device__ __forceinline__ unsigned long long ffma2(unsigned long long a,
                                                    unsigned long long b,
                                                    unsigned long long c) {
    unsigned long long d;
    asm("fma.rn.f32x2 %0, %1, %2, %3;" : "=l"(d) : "l"(a), "l"(b), "l"(c));
    return d;
}
__device__ __forceinline__ unsigned long long fadd2(unsigned long long a,
                                                    unsigned long long b) {
    unsigned long long d;
    asm("add.rn.f32x2 %0, %1, %2;" : "=l"(d) : "l"(a), "l"(b));
    return d;
}
__device__ __forceinline__ unsigned long long pack2(float lo, float hi) {
    unsigned long long d;
    asm("mov.b64 %0, {%1, %2};" : "=l"(d) : "f"(lo), "f"(hi));
    return d;
}

__global__ __launch_bounds__(128, 4)
void dendrite_kernel(const float* __restrict__ x,
                     const float* __restrict__ k,
                     const float* __restrict__ w,
                     const float* __restrict__ q,
                     const float* __restrict__ dend_w,
                     const float* __restrict__ dend_b,
                     const float* __restrict__ lin_w,
                     const float* __restrict__ lin_b,
                     const float* __restrict__ final_w,
                     const float* __restrict__ final_b,
                     const float* __restrict__ ks,
                     float* __restrict__ out)
{
    // dend_w staged per-layer with a zero pad at v=0 so the (excluded) empty
    // subset contributes nothing: sdw[l*1024 + v] = dend_w[l*1023 + v-1], v>=1.
    __shared__ __align__(16) float sdw[NL * 1024];
    __shared__ float sred[NL];

    const int tid = threadIdx.x;
    const int b   = blockIdx.x;      // one batch element per block
    const int l   = tid >> 5;        // warp == one layer
    const int d   = tid & 31;        // lane == dendrite

    for (int i = tid; i < NL * 1024; i += 128) {
        int ll = i >> 10, v = i & 1023;
        sdw[i] = v ? dend_w[ll * 1023 + v - 1] : 0.0f;
    }
    __syncthreads();

    // s_i = sigmoid(k * (w * x - q)), i = 0..9
    float s[NS];
    const int base = (l * ND + d) * NS;
    #pragma unroll
    for (int i = 0; i < NS; ++i) {
        float z = k[base + i] * (w[base + i] * x[b * NS + i] - q[base + i]);
        s[i] = 1.0f / (1.0f + __expf(-z));
    }

    // Subset products. Mask row v (1..1023): bit p (LSB) of v selects s[9-p].
    // Split v = 32*h + lo: low 5 bits -> s[9..5], high 5 bits -> s[4..0].
    float Plo[32], Phi[32];
    Plo[0] = 1.0f; Phi[0] = 1.0f;
    #pragma unroll
    for (int bit = 0; bit < 5; ++bit) {
        const float slo = s[9 - bit];
        const float shi = s[4 - bit];
        #pragma unroll
        for (int u = 0; u < (1 << bit); ++u) {
            Plo[(1 << bit) + u] = Plo[u] * slo;
            Phi[(1 << bit) + u] = Phi[u] * shi;
        }
    }

    // Pack Plo into f32x2 pairs
    unsigned long long Pp[16];
    #pragma unroll
    for (int u = 0; u < 16; ++u) Pp[u] = pack2(Plo[2 * u], Plo[2 * u + 1]);

    // Bilinear form: acc = sum_h Phi[h] * sum_lo sdw[l][32h+lo] * Plo[lo]
    const ulonglong2* row = reinterpret_cast<const ulonglong2*>(sdw + (l << 10));
    unsigned long long acc2 = 0ULL;  // packed (0, 0)
    #pragma unroll
    for (int h = 0; h < 32; ++h) {
        unsigned long long t0 = 0ULL, t1 = 0ULL;
        #pragma unroll
        for (int j = 0; j < 8; ++j) {
            ulonglong2 dv = row[h * 8 + j];          // 4 floats of dend_w (broadcast LDS.128)
            t0 = ffma2(dv.x, Pp[2 * j],     t0);
            t1 = ffma2(dv.y, Pp[2 * j + 1], t1);
        }
        unsigned long long phi2 = pack2(Phi[h], Phi[h]);
        acc2 = ffma2(fadd2(t0, t1), phi2, acc2);
    }
    float alo, ahi;
    asm("mov.b64 {%0, %1}, %2;" : "=f"(alo), "=f"(ahi) : "l"(acc2));

    // dend -> per-layer linear (warp reduce over d) -> final linear + sigmoid
    float dend = alo + ahi + dend_b[l];
    float v = dend * lin_w[l * ND + d];
    #pragma unroll
    for (int off = 16; off; off >>= 1)
        v += __shfl_xor_sync(0xffffffffu, v, off);
    if (d == 0) sred[l] = (v + lin_b[l]) * final_w[l];
    __syncthreads();
    if (tid == 0) {
        float fin = sred[0] + sred[1] + sred[2] + sred[3] + final_b[0];
        out[b] = 1.0f / (1.0f + __expf(-ks[0] * fin));
    }
}

extern "C" void kernel_launch(void* const* d_in, const int* in_sizes, int n_in,
                              void* d_out, int out_size) {
    const float* x       = (const float*)d_in[0];
    const float* k       = (const float*)d_in[1];
    const float* w       = (const float*)d_in[2];
    const float* q       = (const float*)d_in[3];
    const float* dend_w  = (const float*)d_in[4];
    const float* dend_b  = (const float*)d_in[5];
    const float* lin_w   = (const float*)d_in[6];
    const float* lin_b   = (const float*)d_in[7];
    const float* final_w = (const float*)d_in[8];
    const float* final_b = (const float*)d_in[9];
    const float* ks      = (const float*)d_in[10];
    float* out = (float*)d_out;
    dendrite_kernel<<<NB, 128>>>(x, k, w, q, dend_w, dend_b,
                                 lin_w, lin_b, final_w, final_b, ks, out);
}

// round 4
// speedup vs baseline: 1.1063x; 1.1063x over previous
#include <cuda_runtime.h>

#define NS 10
#define ND 32
#define NL 4
#define NB 1024
#define BPT 2          // batch elements per thread

typedef unsigned long long u64;

// ---- packed f32x2 helpers (sm_103a) ----
__device__ __forceinline__ u64 ffma2(u64 a, u64 b, u64 c) {
    u64 d;
    asm("fma.rn.f32x2 %0, %1, %2, %3;" : "=l"(d) : "l"(a), "l"(b), "l"(c));
    return d;
}
__device__ __forceinline__ u64 fadd2(u64 a, u64 b) {
    u64 d;
    asm("add.rn.f32x2 %0, %1, %2;" : "=l"(d) : "l"(a), "l"(b));
    return d;
}
__device__ __forceinline__ u64 pack2(float lo, float hi) {
    u64 d;
    asm("mov.b64 %0, {%1, %2};" : "=l"(d) : "f"(lo), "f"(hi));
    return d;
}
__device__ __forceinline__ float hsum2(u64 v) {
    float lo, hi;
    asm("mov.b64 {%0, %1}, %2;" : "=f"(lo), "=f"(hi) : "l"(v));
    return lo + hi;
}

__global__ __launch_bounds__(128, 4)
void dendrite_kernel(const float* __restrict__ x,
                     const float* __restrict__ k,
                     const float* __restrict__ w,
                     const float* __restrict__ q,
                     const float* __restrict__ dend_w,
                     const float* __restrict__ dend_b,
                     const float* __restrict__ lin_w,
                     const float* __restrict__ lin_b,
                     const float* __restrict__ final_w,
                     const float* __restrict__ final_b,
                     const float* __restrict__ ks,
                     float* __restrict__ out)
{
    // dend_w per-layer with a zero at v=0 so the excluded empty subset drops out
    __shared__ __align__(16) float sdw[NL * 1024];
    __shared__ float sred[BPT][NL];

    const int tid = threadIdx.x;
    const int l   = tid >> 5;        // warp == layer
    const int d   = tid & 31;        // lane == dendrite
    const int b0  = blockIdx.x * BPT;

    for (int i = tid; i < NL * 1024; i += 128) {
        int ll = i >> 10, v = i & 1023;
        sdw[i] = v ? dend_w[ll * 1023 + v - 1] : 0.0f;
    }
    __syncthreads();

    const int base = (l * ND + d) * NS;

    // Per-b setup: s_i = sigmoid(k*(w*x - q)); Pp = packed subset products of
    // low-5 mask bits (bit p of lo -> s[9-p]); sH[p] = s[4-p] for the h-tree.
    u64   PpA[16], PpB[16];
    float sHA[5], sHB[5];
    {
        float Plo[32];
        #pragma unroll
        for (int bb = 0; bb < BPT; ++bb) {
            float s[NS];
            #pragma unroll
            for (int i = 0; i < NS; ++i) {
                float z = k[base + i] * (w[base + i] * x[(b0 + bb) * NS + i] - q[base + i]);
                s[i] = 1.0f / (1.0f + __expf(-z));
            }
            Plo[0] = 1.0f;
            #pragma unroll
            for (int bit = 0; bit < 5; ++bit) {
                const float sv = s[9 - bit];
                #pragma unroll
                for (int u = 0; u < (1 << bit); ++u)
                    Plo[(1 << bit) + u] = Plo[u] * sv;
            }
            u64*   Pp = bb ? PpB : PpA;
            float* sH = bb ? sHB : sHA;
            #pragma unroll
            for (int u = 0; u < 16; ++u) Pp[u] = pack2(Plo[2 * u], Plo[2 * u + 1]);
            #pragma unroll
            for (int p = 0; p < 5; ++p) sH[p] = s[4 - p];
        }
    }

    // Mainloop: g_h = sum_lo sdw[32h+lo]*Plo[lo]; dend = sum_h Phi[h]*g_h
    // evaluated as a streaming binary-counter Horner tree (bit p of h -> s[4-p]).
    const ulonglong2* row = reinterpret_cast<const ulonglong2*>(sdw + (l << 10));
    float lvlA[5], lvlB[5];
    float resA = 0.0f, resB = 0.0f;
    #pragma unroll
    for (int h = 0; h < 32; ++h) {
        u64 t0a = 0ULL, t1a = 0ULL, t0b = 0ULL, t1b = 0ULL;
        #pragma unroll
        for (int j = 0; j < 8; ++j) {
            ulonglong2 dv = row[h * 8 + j];         // broadcast LDS.128, reused for both b
            t0a = ffma2(dv.x, PpA[2 * j],     t0a);
            t1a = ffma2(dv.y, PpA[2 * j + 1], t1a);
            t0b = ffma2(dv.x, PpB[2 * j],     t0b);
            t1b = ffma2(dv.y, PpB[2 * j + 1], t1b);
        }
        float va = hsum2(fadd2(t0a, t1a));
        float vb = hsum2(fadd2(t0b, t1b));
        bool done = false;
        #pragma unroll
        for (int p = 0; p < 5; ++p) {
            if (!done) {
                if ((h >> p) & 1) {
                    va = fmaf(va, sHA[p], lvlA[p]);
                    vb = fmaf(vb, sHB[p], lvlB[p]);
                } else {
                    lvlA[p] = va;
                    lvlB[p] = vb;
                    done = true;
                }
            }
        }
        if (h == 31) { resA = va; resB = vb; }
    }

    // Epilogue: per-layer Linear(D,1) via warp reduce, then Linear(L,1)+sigmoid.
    const float lw = lin_w[l * ND + d];
    float vA = (resA + dend_b[l]) * lw;
    float vB = (resB + dend_b[l]) * lw;
    #pragma unroll
    for (int off = 16; off; off >>= 1) {
        vA += __shfl_xor_sync(0xffffffffu, vA, off);
        vB += __shfl_xor_sync(0xffffffffu, vB, off);
    }
    if (d == 0) {
        const float fw = final_w[l], lb = lin_b[l];
        sred[0][l] = (vA + lb) * fw;
        sred[1][l] = (vB + lb) * fw;
    }
    __syncthreads();
    if (tid < BPT) {
        float fin = sred[tid][0] + sred[tid][1] + sred[tid][2] + sred[tid][3] + final_b[0];
        out[b0 + tid] = 1.0f / (1.0f + __expf(-ks[0] * fin));
    }
}

extern "C" void kernel_launch(void* const* d_in, const int* in_sizes, int n_in,
                              void* d_out, int out_size) {
    const float* x       = (const float*)d_in[0];
    const float* k       = (const float*)d_in[1];
    const float* w       = (const float*)d_in[2];
    const float* q       = (const float*)d_in[3];
    const float* dend_w  = (const float*)d_in[4];
    const float* dend_b  = (const float*)d_in[5];
    const float* lin_w   = (const float*)d_in[6];
    const float* lin_b   = (const float*)d_in[7];
    const float* final_w = (const float*)d_in[8];
    const float* final_b = (const float*)d_in[9];
    const float* ks      = (const float*)d_in[10];
    float* out = (float*)d_out;
    dendrite_kernel<<<NB / BPT, 128>>>(x, k, w, q, dend_w, dend_b,
                                       lin_w, lin_b, final_w, final_b, ks, out);
}